// round 4
// baseline (speedup 1.0000x reference)
#include <cuda_runtime.h>
#include <cuda_bf16.h>
#include <math.h>

// ---------------------------------------------------------------------------
// Problem constants
// ---------------------------------------------------------------------------
#define BB    128      // batch
#define SS    128      // seq len
#define DD    128      // D_K = D_A = D_E
#define NQ1   101      // N_Q + 1
#define NPAD  104      // padded rows (13 warps * 8 rows)
#define QLD   101      // q_matrix row stride

// ---------------------------------------------------------------------------
// Device scratch (static allocation; no cudaMalloc allowed)
// ---------------------------------------------------------------------------
__device__ float g_X1 [BB*SS*384];   // [e_emb | at_emb | a_feat]
__device__ float g_X2 [BB*SS*384];   // [learning_pre | it | learning]
__device__ float g_AL [BB*SS*128];   // all_learning
__device__ float g_IT [BB*SS*128];   // it_emb
__device__ float g_E5x[BB*SS*128];   // e_emb[:, s+1]
__device__ float g_G2 [BB*SS*128];   // z-prefix @ W2abc.T + b2
__device__ float g_G3 [BB*SS*128];
__device__ float g_Cit[BB*SS*128];   // it @ W4c.T + b4
__device__ float g_E5 [BB*SS*128];   // e_next @ W5a.T + b5
// transposed weight blocks, each [k][j] 128x128:
// 0 = W4a, 1 = W4b, 2 = W2d, 3 = W3d, 4 = W5b
__device__ float g_WT [5*128*128];

__device__ __forceinline__ float fsig(float x) {
    return __fdividef(1.0f, 1.0f + __expf(-x));
}

// ---------------------------------------------------------------------------
// Gather 1: build X1, IT, E5x
// ---------------------------------------------------------------------------
__global__ void k_gather1(const int* __restrict__ e_data, const int* __restrict__ a_data,
                          const int* __restrict__ it_data, const int* __restrict__ at_data,
                          const float* __restrict__ e_w, const float* __restrict__ at_w,
                          const float* __restrict__ it_w)
{
    int row = blockIdx.x;
    int k   = threadIdx.x;
    int e  = e_data[row];
    int a  = a_data[row];
    int it = it_data[row];
    int at = at_data[row];
    g_X1[row*384 +       k] = e_w [e *128 + k];
    g_X1[row*384 + 128 + k] = at_w[at*128 + k];
    g_X1[row*384 + 256 + k] = (float)a;
    g_IT[row*128 + k]       = it_w[it*128 + k];
    int s = row & (SS-1);
    g_E5x[row*128 + k] = (s < SS-1) ? e_w[e_data[row+1]*128 + k] : 0.0f;
}

// ---------------------------------------------------------------------------
// Gather 2: build X2 (needs g_AL)
// ---------------------------------------------------------------------------
__global__ void k_gather2()
{
    int row = blockIdx.x;
    int k   = threadIdx.x;
    int s   = row & (SS-1);
    g_X2[row*384 +       k] = (s >= 1) ? g_AL[(row-1)*128 + k] : 0.0f;
    g_X2[row*384 + 128 + k] = g_IT[row*128 + k];
    g_X2[row*384 + 256 + k] = g_AL[row*128 + k];
}

// ---------------------------------------------------------------------------
// Generic tiled SGEMM:  Out[M][128] = X[M][K] @ W[:, woff:woff+K].T + bias
// Block: 512 threads, 64 rows x 128 cols; k-tile 32.
// xsel/osel select __device__ scratch arrays (host cannot pass their addrs).
// ---------------------------------------------------------------------------
__device__ __forceinline__ const float* pick_x(int s) {
    switch (s) { case 0: return g_X1; case 1: return g_X2;
                 case 2: return g_IT; default: return g_E5x; }
}
__device__ __forceinline__ float* pick_o(int s) {
    switch (s) { case 0: return g_AL; case 1: return g_G2; case 2: return g_G3;
                 case 3: return g_Cit; default: return g_E5; }
}

__global__ __launch_bounds__(512) void k_gemm(int xsel, int ldx, int K,
                                              const float* __restrict__ W, int ldw, int woff,
                                              const float* __restrict__ bias, int osel)
{
    __shared__ float Xs[64][33];
    __shared__ float Ws[32][132];
    const float* X = pick_x(xsel);
    float*       O = pick_o(osel);

    int tid  = threadIdx.x;
    int cq   = tid & 31;        // col quad -> j0 = cq*4
    int rq   = tid >> 5;        // 0..15   -> r0 = rq*4
    int row0 = blockIdx.x * 64;

    float4 acc[4];
    acc[0] = make_float4(0,0,0,0); acc[1] = acc[0]; acc[2] = acc[0]; acc[3] = acc[0];

    for (int kt = 0; kt < K; kt += 32) {
        for (int i = tid; i < 64*32; i += 512) {
            int r = i >> 5, kk = i & 31;
            Xs[r][kk] = X[(row0 + r)*ldx + kt + kk];
        }
        for (int i = tid; i < 128*32; i += 512) {
            int j = i >> 5, kk = i & 31;
            Ws[kk][j] = W[j*ldw + woff + kt + kk];
        }
        __syncthreads();
        #pragma unroll
        for (int kk = 0; kk < 32; ++kk) {
            const float4 bv = *(const float4*)&Ws[kk][cq*4];
            const float a0 = Xs[rq*4+0][kk];
            const float a1 = Xs[rq*4+1][kk];
            const float a2 = Xs[rq*4+2][kk];
            const float a3 = Xs[rq*4+3][kk];
            acc[0].x = fmaf(a0,bv.x,acc[0].x); acc[0].y = fmaf(a0,bv.y,acc[0].y);
            acc[0].z = fmaf(a0,bv.z,acc[0].z); acc[0].w = fmaf(a0,bv.w,acc[0].w);
            acc[1].x = fmaf(a1,bv.x,acc[1].x); acc[1].y = fmaf(a1,bv.y,acc[1].y);
            acc[1].z = fmaf(a1,bv.z,acc[1].z); acc[1].w = fmaf(a1,bv.w,acc[1].w);
            acc[2].x = fmaf(a2,bv.x,acc[2].x); acc[2].y = fmaf(a2,bv.y,acc[2].y);
            acc[2].z = fmaf(a2,bv.z,acc[2].z); acc[2].w = fmaf(a2,bv.w,acc[2].w);
            acc[3].x = fmaf(a3,bv.x,acc[3].x); acc[3].y = fmaf(a3,bv.y,acc[3].y);
            acc[3].z = fmaf(a3,bv.z,acc[3].z); acc[3].w = fmaf(a3,bv.w,acc[3].w);
        }
        __syncthreads();
    }
    const float4 bb = *(const float4*)&bias[cq*4];
    #pragma unroll
    for (int i = 0; i < 4; ++i) {
        float4 o = acc[i];
        o.x += bb.x; o.y += bb.y; o.z += bb.z; o.w += bb.w;
        *(float4*)&O[(row0 + rq*4 + i)*128 + cq*4] = o;
    }
}

// ---------------------------------------------------------------------------
// Weight transposes into g_WT[m][k*128+j]
// ---------------------------------------------------------------------------
__global__ void k_transpose(const float* __restrict__ W2, const float* __restrict__ W3,
                            const float* __restrict__ W4, const float* __restrict__ W5)
{
    int k = blockIdx.x;       // 0..127
    int m = blockIdx.y;       // 0..4
    int j = threadIdx.x;      // 0..127
    float v;
    switch (m) {
        case 0: v = W4[j*384 +   0 + k]; break;  // W4a
        case 1: v = W4[j*384 + 128 + k]; break;  // W4b
        case 2: v = W2[j*512 + 384 + k]; break;  // W2d
        case 3: v = W3[j*512 + 384 + k]; break;  // W3d
        default:v = W5[j*256 + 128 + k]; break;  // W5b
    }
    g_WT[m*16384 + k*128 + j] = v;
}

// ---------------------------------------------------------------------------
// Main persistent scan kernel: 1 CTA per batch element, 13 warps.
// smem: h[104][128], W4aT[128][128], ht/LG/c[128], qe/qn[104], red[13][128]
// ---------------------------------------------------------------------------
#define SMEM_FLOATS (13312 + 16384 + 128 + 128 + 128 + 104 + 104 + 13*128 + 16)
#define SMEM_BYTES  (SMEM_FLOATS * 4)

#define ACC4(A, W, xs)                    \
    A.x = fmaf((W).x, (xs), A.x);         \
    A.y = fmaf((W).y, (xs), A.y);         \
    A.z = fmaf((W).z, (xs), A.z);         \
    A.w = fmaf((W).w, (xs), A.w);

__global__ __launch_bounds__(416, 1) void k_main(const float* __restrict__ qm,
                                                 const int* __restrict__ e_data,
                                                 const float* __restrict__ h0,
                                                 float* __restrict__ pred)
{
    extern __shared__ float sm[];
    float* sh_h   = sm;                    // 13312
    float* sh_w   = sh_h  + 13312;         // 16384 (W4aT)
    float* sh_ht  = sh_w  + 16384;         // 128
    float* sh_LG  = sh_ht + 128;           // 128
    float* sh_c   = sh_LG + 128;           // 128
    float* sh_qe  = sh_c  + 128;           // 104
    float* sh_qn  = sh_qe + 104;           // 104
    float* sh_red = sh_qn + 104;           // 13*128
    float* sh_ms  = sh_red + 13*128;       // 16  ([0]=qsum, [1..4] y partials)

    const int b    = blockIdx.x;
    const int tid  = threadIdx.x;
    const int w    = tid >> 5;
    const int lane = tid & 31;
    const int lane4 = lane * 4;

    const float* W2dT = g_WT + 2*16384;
    const float* W3dT = g_WT + 3*16384;
    const float* W4bT = g_WT + 1*16384;
    const float* W5bT = g_WT + 4*16384;

    // ---- load W4aT and h0 into smem, q0 row, zero pred col 0 ----
    for (int i = tid; i < 16384; i += 416) sh_w[i] = g_WT[i];
    for (int i = tid; i < 13312; i += 416) sh_h[i] = (i < NQ1*128) ? h0[i] : 0.0f;
    if (tid < NPAD) {
        int e0 = e_data[b*SS];
        sh_qe[tid] = (tid < NQ1) ? qm[e0*QLD + tid] : 0.0f;
    }
    if (tid == 0) pred[b*SS] = 0.0f;
    __syncthreads();

    // ---- initial h_tilde = (q0 . h0) / sum(q0) ----
    {
        float4 t4 = make_float4(0,0,0,0);
        #pragma unroll
        for (int i = 0; i < 8; ++i) {
            int r = w*8 + i;
            float q = sh_qe[r];
            float4 hv = *(const float4*)&sh_h[r*128 + lane4];
            t4.x = fmaf(q, hv.x, t4.x); t4.y = fmaf(q, hv.y, t4.y);
            t4.z = fmaf(q, hv.z, t4.z); t4.w = fmaf(q, hv.w, t4.w);
        }
        *(float4*)&sh_red[w*128 + lane4] = t4;
        if (w == 12) {
            float s = 0.0f;
            for (int i = lane; i < NPAD; i += 32) s += sh_qe[i];
            #pragma unroll
            for (int o = 16; o; o >>= 1) s += __shfl_down_sync(0xffffffffu, s, o);
            if (lane == 0) sh_ms[0] = s;
        }
    }
    __syncthreads();
    if (tid < 128) {
        float t = 0.0f;
        #pragma unroll
        for (int ww = 0; ww < 13; ++ww) t += sh_red[ww*128 + tid];
        sh_ht[tid] = t / sh_ms[0];
    }
    __syncthreads();

    const float* G2b  = g_G2  + b*SS*128;
    const float* G3b  = g_G3  + b*SS*128;
    const float* Citb = g_Cit + b*SS*128;
    const float* E5b  = g_E5  + b*SS*128;

    for (int s = 0; s < SS-1; ++s) {
        // ---------------- phase 1a: LG GEMVs  |  q row loads -------------
        if (tid < 128) {
            const int j = tid;
            float u2a = G2b[s*128 + j], u2b = 0.0f;
            float u3a = G3b[s*128 + j], u3b = 0.0f;
            #pragma unroll 8
            for (int k = 0; k < 128; k += 2) {
                float ha = sh_ht[k], hb = sh_ht[k+1];
                u2a = fmaf(ha, W2dT[(k  )*128 + j], u2a);
                u2b = fmaf(hb, W2dT[(k+1)*128 + j], u2b);
                u3a = fmaf(ha, W3dT[(k  )*128 + j], u3a);
                u3b = fmaf(hb, W3dT[(k+1)*128 + j], u3b);
            }
            float lg = tanhf(u2a + u2b);
            float gl = fsig(u3a + u3b);
            sh_LG[j] = gl * (lg + 1.0f) * 0.5f;
        } else if (tid < 128 + NPAD) {
            int n  = tid - 128;
            int es = e_data[b*SS + s];
            int en = e_data[b*SS + s + 1];
            sh_qe[n] = (n < NQ1) ? qm[es*QLD + n] : 0.0f;
            sh_qn[n] = (n < NQ1) ? qm[en*QLD + n] : 0.0f;
        }
        __syncthreads();

        // ---------------- phase 1b: c GEMV  |  qsum -----------------------
        if (tid < 128) {
            const int j = tid;
            float ca = Citb[s*128 + j], cb = 0.0f;
            #pragma unroll 8
            for (int k = 0; k < 128; k += 2) {
                ca = fmaf(sh_LG[k  ], W4bT[(k  )*128 + j], ca);
                cb = fmaf(sh_LG[k+1], W4bT[(k+1)*128 + j], cb);
            }
            sh_c[j] = ca + cb;
        } else if (w == 12) {
            float ssum = 0.0f;
            for (int i = lane; i < NPAD; i += 32) ssum += sh_qn[i];
            #pragma unroll
            for (int o = 16; o; o >>= 1) ssum += __shfl_down_sync(0xffffffffu, ssum, o);
            if (lane == 0) sh_ms[0] = ssum;
        }
        __syncthreads();

        // ---------------- phase 2: main 104x128x128 fused GEMM ------------
        float4 LG4 = *(const float4*)&sh_LG[lane4];
        float4 c4  = *(const float4*)&sh_c[lane4];
        float4 tacc = make_float4(0,0,0,0);
        #pragma unroll
        for (int g = 0; g < 2; ++g) {
            const int r0 = w*8 + g*4;
            const float* hr0 = sh_h + r0*128;
            const float* hr1 = hr0 + 128;
            const float* hr2 = hr0 + 256;
            const float* hr3 = hr0 + 384;
            float4 a0 = c4, a1 = c4, a2 = c4, a3 = c4;
            #pragma unroll 4
            for (int k = 0; k < 128; k += 4) {
                const float4 w0 = *(const float4*)&sh_w[(k  )*128 + lane4];
                const float4 w1 = *(const float4*)&sh_w[(k+1)*128 + lane4];
                const float4 w2v= *(const float4*)&sh_w[(k+2)*128 + lane4];
                const float4 w3v= *(const float4*)&sh_w[(k+3)*128 + lane4];
                const float4 x0 = *(const float4*)&hr0[k];
                const float4 x1 = *(const float4*)&hr1[k];
                const float4 x2 = *(const float4*)&hr2[k];
                const float4 x3 = *(const float4*)&hr3[k];
                ACC4(a0, w0, x0.x); ACC4(a0, w1, x0.y); ACC4(a0, w2v, x0.z); ACC4(a0, w3v, x0.w);
                ACC4(a1, w0, x1.x); ACC4(a1, w1, x1.y); ACC4(a1, w2v, x1.z); ACC4(a1, w3v, x1.w);
                ACC4(a2, w0, x2.x); ACC4(a2, w1, x2.y); ACC4(a2, w2v, x2.z); ACC4(a2, w3v, x2.w);
                ACC4(a3, w0, x3.x); ACC4(a3, w1, x3.y); ACC4(a3, w2v, x3.z); ACC4(a3, w3v, x3.w);
            }
            float4 accs[4] = {a0, a1, a2, a3};
            #pragma unroll
            for (int i = 0; i < 4; ++i) {
                int r = r0 + i;
                float qe = sh_qe[r];
                float qn = sh_qn[r];
                float4 hv = *(const float4*)&sh_h[r*128 + lane4];
                float4 p;
                p.x = fsig(accs[i].x); p.y = fsig(accs[i].y);
                p.z = fsig(accs[i].z); p.w = fsig(accs[i].w);
                float4 hn;
                hn.x = fmaf(qe, LG4.x, p.x * hv.x);
                hn.y = fmaf(qe, LG4.y, p.y * hv.y);
                hn.z = fmaf(qe, LG4.z, p.z * hv.z);
                hn.w = fmaf(qe, LG4.w, p.w * hv.w);
                *(float4*)&sh_h[r*128 + lane4] = hn;
                tacc.x = fmaf(qn, hn.x, tacc.x); tacc.y = fmaf(qn, hn.y, tacc.y);
                tacc.z = fmaf(qn, hn.z, tacc.z); tacc.w = fmaf(qn, hn.w, tacc.w);
            }
        }
        *(float4*)&sh_red[w*128 + lane4] = tacc;
        __syncthreads();

        // ---------------- phase 3: new h_tilde ----------------------------
        if (tid < 128) {
            float t = 0.0f;
            #pragma unroll
            for (int ww = 0; ww < 13; ++ww) t += sh_red[ww*128 + tid];
            sh_ht[tid] = t / sh_ms[0];
        }
        __syncthreads();

        // ---------------- phase 4: y output -------------------------------
        if (tid < 128) {
            const int j = tid;
            float ua = E5b[s*128 + j], ub = 0.0f;
            #pragma unroll 8
            for (int k = 0; k < 128; k += 2) {
                ua = fmaf(sh_ht[k  ], W5bT[(k  )*128 + j], ua);
                ub = fmaf(sh_ht[k+1], W5bT[(k+1)*128 + j], ub);
            }
            float sg = fsig(ua + ub);
            #pragma unroll
            for (int o = 16; o; o >>= 1) sg += __shfl_down_sync(0xffffffffu, sg, o);
            if (lane == 0) sh_ms[1 + w] = sg;
        }
        __syncthreads();
        if (tid == 0) {
            pred[b*SS + s + 1] =
                (sh_ms[1] + sh_ms[2] + sh_ms[3] + sh_ms[4]) * (1.0f/128.0f);
        }
        // next iteration's phase1a only touches smem already fenced above
    }
}

// ---------------------------------------------------------------------------
// Launch
// ---------------------------------------------------------------------------
extern "C" void kernel_launch(void* const* d_in, const int* in_sizes, int n_in,
                              void* d_out, int out_size)
{
    const int*   e_data   = (const int*)  d_in[0];
    const int*   a_data   = (const int*)  d_in[1];
    const int*   it_data  = (const int*)  d_in[2];
    const int*   at_data  = (const int*)  d_in[3];
    const float* q_matrix = (const float*)d_in[4];
    const float* e_w      = (const float*)d_in[5];
    const float* at_w     = (const float*)d_in[6];
    const float* it_w     = (const float*)d_in[7];
    const float* h0       = (const float*)d_in[8];
    const float* W1       = (const float*)d_in[9];
    const float* b1       = (const float*)d_in[10];
    const float* W2       = (const float*)d_in[11];
    const float* b2       = (const float*)d_in[12];
    const float* W3       = (const float*)d_in[13];
    const float* b3       = (const float*)d_in[14];
    const float* W4       = (const float*)d_in[15];
    const float* b4       = (const float*)d_in[16];
    const float* W5       = (const float*)d_in[17];
    const float* b5       = (const float*)d_in[18];
    float*       pred     = (float*)d_out;

    cudaFuncSetAttribute(k_main, cudaFuncAttributeMaxDynamicSharedMemorySize, SMEM_BYTES);

    k_gather1<<<BB*SS, 128>>>(e_data, a_data, it_data, at_data, e_w, at_w, it_w);
    k_gemm<<<BB*SS/64, 512>>>(0, 384, 384, W1, 384,   0, b1, 0);  // all_learning
    k_gather2<<<BB*SS, 128>>>();
    k_gemm<<<BB*SS/64, 512>>>(1, 384, 384, W2, 512,   0, b2, 1);  // G2
    k_gemm<<<BB*SS/64, 512>>>(1, 384, 384, W3, 512,   0, b3, 2);  // G3
    k_gemm<<<BB*SS/64, 512>>>(2, 128, 128, W4, 384, 256, b4, 3);  // Cit
    k_gemm<<<BB*SS/64, 512>>>(3, 128, 128, W5, 256,   0, b5, 4);  // E5
    {
        dim3 g(128, 5);
        k_transpose<<<g, 128>>>(W2, W3, W4, W5);
    }
    k_main<<<BB, 416, SMEM_BYTES>>>(q_matrix, e_data, h0, pred);
}